// round 2
// baseline (speedup 1.0000x reference)
#include <cuda_runtime.h>
#include <cuda_bf16.h>

#define SEQ   4096
#define HID   2048
#define NQKVZ 12288
#define CONVD 8192
#define KEYDIM 2048
#define VALDIM 4096

typedef unsigned long long ull;

// ------------ scratch (static device globals; no allocation) ------------
__device__ float g_qkvz [(size_t)SEQ * NQKVZ];
__device__ float g_ba   [SEQ * 64];
__device__ float g_mixed[(size_t)SEQ * CONVD];   // [t][q2048|k2048|v4096] post conv+silu
__device__ float g_qn   [(size_t)SEQ * KEYDIM];  // l2norm(q)*DK^-0.5 per h16
__device__ float g_kn   [(size_t)SEQ * KEYDIM];
__device__ float g_eg   [SEQ * 32];
__device__ float g_beta [SEQ * 32];
__device__ float g_core [(size_t)SEQ * VALDIM];
__device__ float g_gated[(size_t)SEQ * VALDIM];

// ------------ f32x2 helpers ------------
__device__ __forceinline__ ull pk2(float a, float b){ ull r; asm("mov.b64 %0,{%1,%2};":"=l"(r):"f"(a),"f"(b)); return r; }
__device__ __forceinline__ void upk2(ull v, float& a, float& b){ asm("mov.b64 {%0,%1},%2;":"=f"(a),"=f"(b):"l"(v)); }
__device__ __forceinline__ ull fma2(ull a, ull b, ull c){ ull d; asm("fma.rn.f32x2 %0,%1,%2,%3;":"=l"(d):"l"(a),"l"(b),"l"(c)); return d; }
__device__ __forceinline__ ull mul2(ull a, ull b){ ull d; asm("mul.rn.f32x2 %0,%1,%2;":"=l"(d):"l"(a),"l"(b)); return d; }
__device__ __forceinline__ ull add2(ull a, ull b){ ull d; asm("add.rn.f32x2 %0,%1,%2;":"=l"(d):"l"(a),"l"(b)); return d; }

__device__ __forceinline__ void mma_bf16(float* c, const unsigned* a, const unsigned* b){
    asm volatile("mma.sync.aligned.m16n8k16.row.col.f32.bf16.bf16.f32 "
        "{%0,%1,%2,%3},{%4,%5,%6,%7},{%8,%9},{%0,%1,%2,%3};\n"
        : "+f"(c[0]),"+f"(c[1]),"+f"(c[2]),"+f"(c[3])
        : "r"(a[0]),"r"(a[1]),"r"(a[2]),"r"(a[3]),"r"(b[0]),"r"(b[1]));
}

#define ASTR 40

// ------------ 128x128-tile GEMM, fp32 via 3-pass bf16 split ------------
__global__ __launch_bounds__(256) void gemm3(const float* __restrict__ A,
                                             const float* __restrict__ B,
                                             float* __restrict__ C,
                                             int M, int N, int K) {
    __shared__ __align__(16) __nv_bfloat16 sAh[128*ASTR], sAl[128*ASTR];
    __shared__ __align__(16) __nv_bfloat16 sBh[128*ASTR], sBl[128*ASTR];
    const int tid = threadIdx.x;
    const int bm = blockIdx.y * 128, bn = blockIdx.x * 128;
    const int warp = tid >> 5, lane = tid & 31;
    const int wm = (warp >> 2) * 64, wn = (warp & 3) * 32;

    float acc[4][4][4];
    #pragma unroll
    for (int i=0;i<4;i++)
      #pragma unroll
      for (int j=0;j<4;j++)
        #pragma unroll
        for (int k=0;k<4;k++) acc[i][j][k]=0.f;

    for (int k0 = 0; k0 < K; k0 += 32) {
        float4 av[4], bv[4];
        #pragma unroll
        for (int i=0;i<4;i++){
            int id = tid + i*256;
            av[i] = *(const float4*)(A + (size_t)(bm + (id>>3))*K + k0 + (id&7)*4);
            bv[i] = *(const float4*)(B + (size_t)(k0 + (id>>5))*N + bn + (id&31)*4);
        }
        __syncthreads();
        #pragma unroll
        for (int i=0;i<4;i++){
            int id = tid + i*256;
            int ar = id>>3, ac = (id&7)*4;
            const float* f = (const float*)&av[i];
            #pragma unroll
            for (int j=0;j<4;j++){
                __nv_bfloat16 h = __float2bfloat16(f[j]);
                sAh[ar*ASTR+ac+j] = h;
                sAl[ar*ASTR+ac+j] = __float2bfloat16(f[j] - __bfloat162float(h));
            }
            int br = id>>5, bc = (id&31)*4;
            const float* g2 = (const float*)&bv[i];
            #pragma unroll
            for (int j=0;j<4;j++){
                __nv_bfloat16 h = __float2bfloat16(g2[j]);
                sBh[(bc+j)*ASTR+br] = h;
                sBl[(bc+j)*ASTR+br] = __float2bfloat16(g2[j] - __bfloat162float(h));
            }
        }
        __syncthreads();
        #pragma unroll
        for (int ks=0; ks<2; ks++){
            unsigned ah[4][4], al[4][4], bh[4][2], bl[4][2];
            const int kof = ks*16;
            #pragma unroll
            for (int mt=0;mt<4;mt++){
                int r = wm + mt*16 + (lane>>2), cc = kof + (lane&3)*2;
                ah[mt][0]=*(const unsigned*)&sAh[ r   *ASTR+cc  ];
                ah[mt][1]=*(const unsigned*)&sAh[(r+8)*ASTR+cc  ];
                ah[mt][2]=*(const unsigned*)&sAh[ r   *ASTR+cc+8];
                ah[mt][3]=*(const unsigned*)&sAh[(r+8)*ASTR+cc+8];
                al[mt][0]=*(const unsigned*)&sAl[ r   *ASTR+cc  ];
                al[mt][1]=*(const unsigned*)&sAl[(r+8)*ASTR+cc  ];
                al[mt][2]=*(const unsigned*)&sAl[ r   *ASTR+cc+8];
                al[mt][3]=*(const unsigned*)&sAl[(r+8)*ASTR+cc+8];
            }
            #pragma unroll
            for (int nt=0;nt<4;nt++){
                int nc = wn + nt*8 + (lane>>2), kr = kof + (lane&3)*2;
                bh[nt][0]=*(const unsigned*)&sBh[nc*ASTR+kr  ];
                bh[nt][1]=*(const unsigned*)&sBh[nc*ASTR+kr+8];
                bl[nt][0]=*(const unsigned*)&sBl[nc*ASTR+kr  ];
                bl[nt][1]=*(const unsigned*)&sBl[nc*ASTR+kr+8];
            }
            #pragma unroll
            for (int mt=0;mt<4;mt++)
              #pragma unroll
              for (int nt=0;nt<4;nt++){
                  mma_bf16(acc[mt][nt], ah[mt], bh[nt]);
                  mma_bf16(acc[mt][nt], ah[mt], bl[nt]);
                  mma_bf16(acc[mt][nt], al[mt], bh[nt]);
              }
        }
    }
    #pragma unroll
    for (int mt=0;mt<4;mt++){
        int r = bm + wm + mt*16 + (lane>>2);
        #pragma unroll
        for (int nt=0;nt<4;nt++){
            int c = bn + wn + nt*8 + (lane&3)*2;
            *(float2*)(C + (size_t) r   *N + c) = make_float2(acc[mt][nt][0], acc[mt][nt][1]);
            *(float2*)(C + (size_t)(r+8)*N + c) = make_float2(acc[mt][nt][2], acc[mt][nt][3]);
        }
    }
}

// ------------ ba = H @ W_ba  (N=64) ------------
__global__ __launch_bounds__(256) void gemm_ba(const float* __restrict__ A,
                                               const float* __restrict__ B) {
    int r = blockIdx.x*4 + (threadIdx.x>>6);
    int c = threadIdx.x & 63;
    const float* ar = A + (size_t)r*HID;
    float acc = 0.f;
    #pragma unroll 4
    for (int k=0;k<HID;k+=4){
        float4 a = *(const float4*)(ar+k);
        acc += a.x*B[(k  )*64+c] + a.y*B[(k+1)*64+c]
             + a.z*B[(k+2)*64+c] + a.w*B[(k+3)*64+c];
    }
    g_ba[r*64+c] = acc;
}

// ------------ causal depthwise conv(4) + silu ------------
__global__ __launch_bounds__(128) void conv_kernel(const float* __restrict__ cw) {
    int c  = blockIdx.x*128 + threadIdx.x;   // 0..8191
    int t0 = blockIdx.y*64;
    int col;
    if (c < 2048)      col = (c>>7)*768 + (c&127);
    else if (c < 4096) { int cc=c-2048; col = (cc>>7)*768 + 128 + (cc&127); }
    else               { int cc=c-4096; col = (cc>>8)*768 + 256 + (cc&255); }
    float4 w = *(const float4*)(cw + c*4);
    float x0=0.f, x1=0.f, x2=0.f;
    if (t0 >= 3) {
        x0 = g_qkvz[(size_t)(t0-3)*NQKVZ + col];
        x1 = g_qkvz[(size_t)(t0-2)*NQKVZ + col];
        x2 = g_qkvz[(size_t)(t0-1)*NQKVZ + col];
    }
    for (int t=t0; t<t0+64; t++) {
        float x3 = g_qkvz[(size_t)t*NQKVZ + col];
        float y = x0*w.x + x1*w.y + x2*w.z + x3*w.w;
        g_mixed[(size_t)t*CONVD + c] = y / (1.f + expf(-y));
        x0=x1; x1=x2; x2=x3;
    }
}

// ------------ l2norm q/k, gates ------------
__global__ __launch_bounds__(256) void prep_kernel(const float* __restrict__ Alog,
                                                   const float* __restrict__ dtb) {
    int t = blockIdx.x;
    int warp = threadIdx.x>>5, lane = threadIdx.x&31;
    #pragma unroll
    for (int i=0;i<4;i++){
        int row = warp*4+i;           // 0-15 q heads, 16-31 k heads
        int isK = row>=16, h = row&15;
        const float* src = g_mixed + (size_t)t*CONVD + (isK?2048:0) + h*128;
        float4 v = *(const float4*)(src + lane*4);
        float ss = v.x*v.x+v.y*v.y+v.z*v.z+v.w*v.w;
        ss += __shfl_xor_sync(~0u, ss, 16);
        ss += __shfl_xor_sync(~0u, ss, 8);
        ss += __shfl_xor_sync(~0u, ss, 4);
        ss += __shfl_xor_sync(~0u, ss, 2);
        ss += __shfl_xor_sync(~0u, ss, 1);
        float sc = rsqrtf(ss + 1e-6f);
        if (!isK) sc *= 0.08838834764831845f;
        float* dst = (isK ? g_kn : g_qn) + (size_t)t*KEYDIM + h*128 + lane*4;
        *(float4*)dst = make_float4(v.x*sc, v.y*sc, v.z*sc, v.w*sc);
    }
    if (threadIdx.x < 32) {
        int h32 = threadIdx.x, h16 = h32>>1, j = h32&1;
        float b = g_ba[t*64 + h16*4 + j];
        float a = g_ba[t*64 + h16*4 + 2 + j];
        float x = a + dtb[h32];
        float sp = (x > 20.f) ? x : log1pf(expf(x));
        g_eg  [t*32 + h32] = expf(-expf(Alog[h32]) * sp);
        g_beta[t*32 + h32] = 1.f / (1.f + expf(-b));
    }
}

// ------------ gated delta-rule scan ------------
// block = (head h, 16-col v block); warp owns 4 cols; lane = (vg=lane>>3, kg=lane&7)
// lane holds S[kg*16..+15, v] packed as 8 f32x2.
__global__ __launch_bounds__(128) void scan_kernel() {
    int h = blockIdx.x>>3, vb = blockIdx.x&7;
    int warp = threadIdx.x>>5, lane = threadIdx.x&31;
    int kg = lane&7, vg = lane>>3;
    int v = vb*16 + warp*4 + vg, h16 = h>>1;
    const float* kp = g_kn + h16*128 + kg*16;
    const float* qp = g_qn + h16*128 + kg*16;
    const float* vp = g_mixed + 4096 + h*128 + v;
    const float* ep = g_eg + h;
    const float* bp = g_beta + h;
    float* op = g_core + h*128 + v;

    ull s[8];
    #pragma unroll
    for (int i=0;i<8;i++) s[i]=0ull;

    #pragma unroll 2
    for (int t=0; t<SEQ; t++) {
        ull kf[8], qf[8];
        const ulonglong2* kk = (const ulonglong2*)(kp + (size_t)t*KEYDIM);
        const ulonglong2* qq = (const ulonglong2*)(qp + (size_t)t*KEYDIM);
        #pragma unroll
        for (int i=0;i<4;i++){
            ulonglong2 a = kk[i]; kf[2*i]=a.x; kf[2*i+1]=a.y;
            ulonglong2 b = qq[i]; qf[2*i]=b.x; qf[2*i+1]=b.y;
        }
        float vv = vp[(size_t)t*CONVD];
        float ee = ep[(size_t)t*32];
        float bt = bp[(size_t)t*32];

        // sk = S_old^T k (this lane's 16-row partial)
        ull a0 = mul2(s[0], kf[0]), a1 = mul2(s[1], kf[1]);
        a0 = fma2(s[2], kf[2], a0); a1 = fma2(s[3], kf[3], a1);
        a0 = fma2(s[4], kf[4], a0); a1 = fma2(s[5], kf[5], a1);
        a0 = fma2(s[6], kf[6], a0); a1 = fma2(s[7], kf[7], a1);
        a0 = add2(a0, a1);
        float x, y; upk2(a0, x, y);
        float sk = x + y;
        sk += __shfl_xor_sync(~0u, sk, 1);
        sk += __shfl_xor_sync(~0u, sk, 2);
        sk += __shfl_xor_sync(~0u, sk, 4);
        float delta = (vv - ee*sk) * bt;
        // S = ee*S + k*delta
        ull e2 = pk2(ee, ee), d2 = pk2(delta, delta);
        #pragma unroll
        for (int i=0;i<8;i++) s[i] = fma2(s[i], e2, mul2(kf[i], d2));
        // out = S^T q
        ull q0 = mul2(s[0], qf[0]), q1 = mul2(s[1], qf[1]);
        q0 = fma2(s[2], qf[2], q0); q1 = fma2(s[3], qf[3], q1);
        q0 = fma2(s[4], qf[4], q0); q1 = fma2(s[5], qf[5], q1);
        q0 = fma2(s[6], qf[6], q0); q1 = fma2(s[7], qf[7], q1);
        q0 = add2(q0, q1);
        float ox, oy; upk2(q0, ox, oy);
        float o = ox + oy;
        o += __shfl_xor_sync(~0u, o, 1);
        o += __shfl_xor_sync(~0u, o, 2);
        o += __shfl_xor_sync(~0u, o, 4);
        if (kg == 0) op[(size_t)t*VALDIM] = o;
    }
}

// ------------ RMS norm + silu(z) gate ------------
__global__ __launch_bounds__(256) void gate_kernel(const float* __restrict__ nw) {
    int t = blockIdx.x;
    int warp = threadIdx.x>>5, lane = threadIdx.x&31;
    #pragma unroll
    for (int i=0;i<4;i++){
        int h = warp*4 + i;
        const float* cp = g_core + (size_t)t*VALDIM + h*128;
        float4 c = *(const float4*)(cp + lane*4);
        float ss = c.x*c.x + c.y*c.y + c.z*c.z + c.w*c.w;
        ss += __shfl_xor_sync(~0u, ss, 16);
        ss += __shfl_xor_sync(~0u, ss, 8);
        ss += __shfl_xor_sync(~0u, ss, 4);
        ss += __shfl_xor_sync(~0u, ss, 2);
        ss += __shfl_xor_sync(~0u, ss, 1);
        float sc = rsqrtf(ss*(1.f/128.f) + 1e-6f);
        const float* zp = g_qkvz + (size_t)t*NQKVZ + (h>>1)*768 + 512 + (h&1)*128;
        float4 z = *(const float4*)(zp + lane*4);
        float4 w = *(const float4*)(nw + lane*4);
        float4 o;
        o.x = c.x*sc*w.x * (z.x/(1.f+expf(-z.x)));
        o.y = c.y*sc*w.y * (z.y/(1.f+expf(-z.y)));
        o.z = c.z*sc*w.z * (z.z/(1.f+expf(-z.z)));
        o.w = c.w*sc*w.w * (z.w/(1.f+expf(-z.w)));
        *(float4*)(g_gated + (size_t)t*VALDIM + h*128 + lane*4) = o;
    }
}

extern "C" void kernel_launch(void* const* d_in, const int* in_sizes, int n_in,
                              void* d_out, int out_size) {
    const float* H     = (const float*)d_in[0];
    const float* Wqkvz = (const float*)d_in[1];
    const float* Wba   = (const float*)d_in[2];
    const float* convw = (const float*)d_in[3];
    const float* Alog  = (const float*)d_in[4];
    const float* dtb   = (const float*)d_in[5];
    const float* nw    = (const float*)d_in[6];
    const float* Wout  = (const float*)d_in[7];
    float* out = (float*)d_out;

    float *qkvz, *gated;
    cudaGetSymbolAddress((void**)&qkvz,  g_qkvz);
    cudaGetSymbolAddress((void**)&gated, g_gated);

    gemm3<<<dim3(NQKVZ/128, SEQ/128), 256>>>(H, Wqkvz, qkvz, SEQ, NQKVZ, HID);
    gemm_ba<<<SEQ/4, 256>>>(H, Wba);
    conv_kernel<<<dim3(CONVD/128, SEQ/64), 128>>>(convw);
    prep_kernel<<<SEQ, 256>>>(Alog, dtb);
    scan_kernel<<<256, 128>>>();
    gate_kernel<<<SEQ, 256>>>(nw);
    gemm3<<<dim3(HID/128, SEQ/128), 256>>>(gated, Wout, out, SEQ, HID, VALDIM);
}

// round 3
// speedup vs baseline: 2.2898x; 2.2898x over previous
#include <cuda_runtime.h>
#include <cuda_bf16.h>
#include <cstdint>

#define SEQ   4096
#define HID   2048
#define NQKVZ 12288
#define CONVD 8192
#define KEYDIM 2048
#define VALDIM 4096

typedef unsigned long long ull;

// ------------ scratch (static device globals; no allocation) ------------
__device__ float g_qkvz [(size_t)SEQ * NQKVZ];
__device__ float g_ba   [SEQ * 64];
__device__ float g_mixed[(size_t)SEQ * CONVD];
__device__ float g_qn   [(size_t)SEQ * KEYDIM];
__device__ float g_kn   [(size_t)SEQ * KEYDIM];
__device__ float g_eg   [SEQ * 32];
__device__ float g_beta [SEQ * 32];
__device__ float g_core [(size_t)SEQ * VALDIM];
__device__ float g_gated[(size_t)SEQ * VALDIM];

// pre-split bf16 hi/lo operands
__device__ __nv_bfloat16 g_Hh [(size_t)SEQ * HID];
__device__ __nv_bfloat16 g_Hl [(size_t)SEQ * HID];
__device__ __nv_bfloat16 g_W1h[(size_t)NQKVZ * HID];   // transposed: [n][k]
__device__ __nv_bfloat16 g_W1l[(size_t)NQKVZ * HID];
__device__ __nv_bfloat16 g_Gh [(size_t)SEQ * VALDIM];
__device__ __nv_bfloat16 g_Gl [(size_t)SEQ * VALDIM];
__device__ __nv_bfloat16 g_W2h[(size_t)HID * VALDIM];  // transposed: [n=2048][k=4096]
__device__ __nv_bfloat16 g_W2l[(size_t)HID * VALDIM];

// ------------ f32x2 helpers ------------
__device__ __forceinline__ ull pk2(float a, float b){ ull r; asm("mov.b64 %0,{%1,%2};":"=l"(r):"f"(a),"f"(b)); return r; }
__device__ __forceinline__ void upk2(ull v, float& a, float& b){ asm("mov.b64 {%0,%1},%2;":"=f"(a),"=f"(b):"l"(v)); }
__device__ __forceinline__ ull fma2(ull a, ull b, ull c){ ull d; asm("fma.rn.f32x2 %0,%1,%2,%3;":"=l"(d):"l"(a),"l"(b),"l"(c)); return d; }
__device__ __forceinline__ ull mul2(ull a, ull b){ ull d; asm("mul.rn.f32x2 %0,%1,%2;":"=l"(d):"l"(a),"l"(b)); return d; }
__device__ __forceinline__ ull add2(ull a, ull b){ ull d; asm("add.rn.f32x2 %0,%1,%2;":"=l"(d):"l"(a),"l"(b)); return d; }

__device__ __forceinline__ void mma_bf16(float* c, const unsigned* a, const unsigned* b){
    asm volatile("mma.sync.aligned.m16n8k16.row.col.f32.bf16.bf16.f32 "
        "{%0,%1,%2,%3},{%4,%5,%6,%7},{%8,%9},{%0,%1,%2,%3};\n"
        : "+f"(c[0]),"+f"(c[1]),"+f"(c[2]),"+f"(c[3])
        : "r"(a[0]),"r"(a[1]),"r"(a[2]),"r"(a[3]),"r"(b[0]),"r"(b[1]));
}
__device__ __forceinline__ void cp16(uint32_t dst, const void* src){
    asm volatile("cp.async.cg.shared.global [%0], [%1], 16;" :: "r"(dst), "l"(src));
}
__device__ __forceinline__ void ldsm4(unsigned* r, uint32_t a){
    asm volatile("ldmatrix.sync.aligned.m8n8.x4.shared.b16 {%0,%1,%2,%3},[%4];"
        : "=r"(r[0]),"=r"(r[1]),"=r"(r[2]),"=r"(r[3]) : "r"(a));
}
__device__ __forceinline__ void ldsm2(unsigned* r, uint32_t a){
    asm volatile("ldmatrix.sync.aligned.m8n8.x2.shared.b16 {%0,%1},[%2];"
        : "=r"(r[0]),"=r"(r[1]) : "r"(a));
}

// ------------ elementwise fp32 -> bf16 hi/lo split ------------
__global__ __launch_bounds__(256) void split_ew(const float* __restrict__ in,
                                                __nv_bfloat16* __restrict__ oh,
                                                __nv_bfloat16* __restrict__ ol,
                                                size_t n4) {
    size_t i = (size_t)blockIdx.x*256 + threadIdx.x;
    size_t stride = (size_t)gridDim.x*256;
    for (; i < n4; i += stride) {
        float4 v = ((const float4*)in)[i];
        __nv_bfloat16 h0=__float2bfloat16(v.x), h1=__float2bfloat16(v.y),
                      h2=__float2bfloat16(v.z), h3=__float2bfloat16(v.w);
        __nv_bfloat162 H0 = {h0,h1}, H1 = {h2,h3};
        __nv_bfloat162 L0 = {__float2bfloat16(v.x-__bfloat162float(h0)),
                             __float2bfloat16(v.y-__bfloat162float(h1))};
        __nv_bfloat162 L1 = {__float2bfloat16(v.z-__bfloat162float(h2)),
                             __float2bfloat16(v.w-__bfloat162float(h3))};
        ((__nv_bfloat162*)oh)[2*i]   = H0; ((__nv_bfloat162*)oh)[2*i+1] = H1;
        ((__nv_bfloat162*)ol)[2*i]   = L0; ((__nv_bfloat162*)ol)[2*i+1] = L1;
    }
}

// ------------ transpose + split: in[K][N] -> out[n][k] hi/lo ------------
__global__ __launch_bounds__(256) void splitT(const float* __restrict__ in,
                                              __nv_bfloat16* __restrict__ oh,
                                              __nv_bfloat16* __restrict__ ol,
                                              int K, int N) {
    __shared__ float tile[32][33];
    int n0 = blockIdx.x*32, k0 = blockIdx.y*32;
    int tx = threadIdx.x & 31, ty = threadIdx.x >> 5;   // ty 0..7
    #pragma unroll
    for (int j = 0; j < 32; j += 8)
        tile[ty+j][tx] = in[(size_t)(k0+ty+j)*N + n0 + tx];
    __syncthreads();
    #pragma unroll
    for (int j = 0; j < 32; j += 8) {
        float v = tile[tx][ty+j];
        __nv_bfloat16 h = __float2bfloat16(v);
        size_t o = (size_t)(n0+ty+j)*K + k0 + tx;
        oh[o] = h;
        ol[o] = __float2bfloat16(v - __bfloat162float(h));
    }
}

// ------------ pipelined split-bf16 GEMM: C[M][N] = A[M][K] * B^T, B stored [N][K]
#define STG_BYTES 32768   // 4 tiles x 8KB per stage
__global__ __launch_bounds__(256) void gemm_sp(const __nv_bfloat16* __restrict__ Ah,
                                               const __nv_bfloat16* __restrict__ Al,
                                               const __nv_bfloat16* __restrict__ Bh,
                                               const __nv_bfloat16* __restrict__ Bl,
                                               float* __restrict__ C,
                                               int M, int N, int K) {
    extern __shared__ char smem[];
    uint32_t sbase = (uint32_t)__cvta_generic_to_shared(smem);
    const int tid = threadIdx.x;
    const int bm = blockIdx.x*128, bn = blockIdx.y*128;
    const int warp = tid >> 5, lane = tid & 31;
    const int wm = (warp >> 2)*64, wn = (warp & 3)*32;

    float acc[4][4][4];
    #pragma unroll
    for (int i=0;i<4;i++)
      #pragma unroll
      for (int j=0;j<4;j++)
        #pragma unroll
        for (int k=0;k<4;k++) acc[i][j][k]=0.f;

    // per-thread load assignment: 2 chunks per tile-array per stage
    const int id0 = tid, id1 = tid + 256;     // 0..511 => row=id>>2, c=id&3
    auto load_stage = [&](int st, int k0){
        uint32_t so = sbase + st*STG_BYTES;
        #pragma unroll
        for (int i=0;i<2;i++){
            int id  = i ? id1 : id0;
            int row = id >> 2, c = id & 3;
            uint32_t d = row*64 + ((c ^ ((row>>1)&3))<<4);
            size_t ga = (size_t)(bm+row)*K + k0 + c*8;
            size_t gb = (size_t)(bn+row)*K + k0 + c*8;
            cp16(so           + d, Ah + ga);
            cp16(so +  8192   + d, Al + ga);
            cp16(so + 16384   + d, Bh + gb);
            cp16(so + 24576   + d, Bl + gb);
        }
    };

    const int NK = K >> 5;
    load_stage(0, 0);
    asm volatile("cp.async.commit_group;");

    for (int it = 0; it < NK; it++) {
        if (it + 1 < NK) load_stage((it+1)&1, (it+1)*32);
        asm volatile("cp.async.commit_group;");
        asm volatile("cp.async.wait_group 1;");
        __syncthreads();

        uint32_t so = sbase + (it&1)*STG_BYTES;
        #pragma unroll
        for (int ks=0; ks<2; ks++){
            unsigned ah[4][4], al[4][4], bh[4][2], bl[4][2];
            #pragma unroll
            for (int mt=0; mt<4; mt++){
                int row = wm + mt*16 + (lane&15);
                int ch  = ks*2 + (lane>>4);
                uint32_t off = row*64 + ((ch ^ ((row>>1)&3))<<4);
                ldsm4(ah[mt], so + off);
                ldsm4(al[mt], so + 8192 + off);
            }
            #pragma unroll
            for (int nt=0; nt<4; nt++){
                int row = wn + nt*8 + (lane&7);
                int ch  = ks*2 + ((lane&15)>>3);
                uint32_t off = row*64 + ((ch ^ ((row>>1)&3))<<4);
                ldsm2(bh[nt], so + 16384 + off);
                ldsm2(bl[nt], so + 24576 + off);
            }
            #pragma unroll
            for (int mt=0; mt<4; mt++)
              #pragma unroll
              for (int nt=0; nt<4; nt++){
                  mma_bf16(acc[mt][nt], ah[mt], bh[nt]);
                  mma_bf16(acc[mt][nt], ah[mt], bl[nt]);
                  mma_bf16(acc[mt][nt], al[mt], bh[nt]);
              }
        }
        __syncthreads();
    }

    #pragma unroll
    for (int mt=0; mt<4; mt++){
        int r = bm + wm + mt*16 + (lane>>2);
        #pragma unroll
        for (int nt=0; nt<4; nt++){
            int c = bn + wn + nt*8 + (lane&3)*2;
            *(float2*)(C + (size_t) r   *N + c) = make_float2(acc[mt][nt][0], acc[mt][nt][1]);
            *(float2*)(C + (size_t)(r+8)*N + c) = make_float2(acc[mt][nt][2], acc[mt][nt][3]);
        }
    }
}

// ------------ ba = H @ W_ba  (N=64) ------------
__global__ __launch_bounds__(256) void gemm_ba(const float* __restrict__ A,
                                               const float* __restrict__ B) {
    int r = blockIdx.x*4 + (threadIdx.x>>6);
    int c = threadIdx.x & 63;
    const float* ar = A + (size_t)r*HID;
    float acc = 0.f;
    #pragma unroll 4
    for (int k=0;k<HID;k+=4){
        float4 a = *(const float4*)(ar+k);
        acc += a.x*B[(k  )*64+c] + a.y*B[(k+1)*64+c]
             + a.z*B[(k+2)*64+c] + a.w*B[(k+3)*64+c];
    }
    g_ba[r*64+c] = acc;
}

// ------------ causal depthwise conv(4) + silu ------------
__global__ __launch_bounds__(128) void conv_kernel(const float* __restrict__ cw) {
    int c  = blockIdx.x*128 + threadIdx.x;
    int t0 = blockIdx.y*64;
    int col;
    if (c < 2048)      col = (c>>7)*768 + (c&127);
    else if (c < 4096) { int cc=c-2048; col = (cc>>7)*768 + 128 + (cc&127); }
    else               { int cc=c-4096; col = (cc>>8)*768 + 256 + (cc&255); }
    float4 w = *(const float4*)(cw + c*4);
    float x0=0.f, x1=0.f, x2=0.f;
    if (t0 >= 3) {
        x0 = g_qkvz[(size_t)(t0-3)*NQKVZ + col];
        x1 = g_qkvz[(size_t)(t0-2)*NQKVZ + col];
        x2 = g_qkvz[(size_t)(t0-1)*NQKVZ + col];
    }
    #pragma unroll 4
    for (int t=t0; t<t0+64; t++) {
        float x3 = g_qkvz[(size_t)t*NQKVZ + col];
        float y = x0*w.x + x1*w.y + x2*w.z + x3*w.w;
        g_mixed[(size_t)t*CONVD + c] = y / (1.f + expf(-y));
        x0=x1; x1=x2; x2=x3;
    }
}

// ------------ l2norm q/k, gates ------------
__global__ __launch_bounds__(256) void prep_kernel(const float* __restrict__ Alog,
                                                   const float* __restrict__ dtb) {
    int t = blockIdx.x;
    int warp = threadIdx.x>>5, lane = threadIdx.x&31;
    #pragma unroll
    for (int i=0;i<4;i++){
        int row = warp*4+i;
        int isK = row>=16, h = row&15;
        const float* src = g_mixed + (size_t)t*CONVD + (isK?2048:0) + h*128;
        float4 v = *(const float4*)(src + lane*4);
        float ss = v.x*v.x+v.y*v.y+v.z*v.z+v.w*v.w;
        ss += __shfl_xor_sync(~0u, ss, 16);
        ss += __shfl_xor_sync(~0u, ss, 8);
        ss += __shfl_xor_sync(~0u, ss, 4);
        ss += __shfl_xor_sync(~0u, ss, 2);
        ss += __shfl_xor_sync(~0u, ss, 1);
        float sc = rsqrtf(ss + 1e-6f);
        if (!isK) sc *= 0.08838834764831845f;
        float* dst = (isK ? g_kn : g_qn) + (size_t)t*KEYDIM + h*128 + lane*4;
        *(float4*)dst = make_float4(v.x*sc, v.y*sc, v.z*sc, v.w*sc);
    }
    if (threadIdx.x < 32) {
        int h32 = threadIdx.x, h16 = h32>>1, j = h32&1;
        float b = g_ba[t*64 + h16*4 + j];
        float a = g_ba[t*64 + h16*4 + 2 + j];
        float x = a + dtb[h32];
        float sp = (x > 20.f) ? x : log1pf(expf(x));
        g_eg  [t*32 + h32] = expf(-expf(Alog[h32]) * sp);
        g_beta[t*32 + h32] = 1.f / (1.f + expf(-b));
    }
}

// ------------ gated delta-rule scan (register double-buffered) ------------
__global__ __launch_bounds__(128) void scan_kernel() {
    int h = blockIdx.x>>3, vb = blockIdx.x&7;
    int warp = threadIdx.x>>5, lane = threadIdx.x&31;
    int kg = lane&7, vg = lane>>3;
    int v = vb*16 + warp*4 + vg, h16 = h>>1;
    const float* kp = g_kn + h16*128 + kg*16;
    const float* qp = g_qn + h16*128 + kg*16;
    const float* vp = g_mixed + 4096 + h*128 + v;
    const float* ep = g_eg + h;
    const float* bp = g_beta + h;
    float* op = g_core + h*128 + v;

    ull s[8];
    #pragma unroll
    for (int i=0;i<8;i++) s[i]=0ull;

    ull kA[8], qA[8]; float vA, eA, bA;
    auto LOAD = [&](int t, ull* kf, ull* qf, float& vv, float& ee, float& bt){
        const ulonglong2* kk = (const ulonglong2*)(kp + (size_t)t*KEYDIM);
        const ulonglong2* qq = (const ulonglong2*)(qp + (size_t)t*KEYDIM);
        #pragma unroll
        for (int i=0;i<4;i++){
            ulonglong2 a = kk[i]; kf[2*i]=a.x; kf[2*i+1]=a.y;
            ulonglong2 b = qq[i]; qf[2*i]=b.x; qf[2*i+1]=b.y;
        }
        vv = vp[(size_t)t*CONVD];
        ee = ep[(size_t)t*32];
        bt = bp[(size_t)t*32];
    };
    LOAD(0, kA, qA, vA, eA, bA);

    #pragma unroll 2
    for (int t=0; t<SEQ; t++) {
        ull kB[8], qB[8]; float vB, eB, bB;
        if (t+1 < SEQ) LOAD(t+1, kB, qB, vB, eB, bB);

        // sk = S^T k (16-row partial)
        ull a0 = mul2(s[0], kA[0]), a1 = mul2(s[1], kA[1]);
        a0 = fma2(s[2], kA[2], a0); a1 = fma2(s[3], kA[3], a1);
        a0 = fma2(s[4], kA[4], a0); a1 = fma2(s[5], kA[5], a1);
        a0 = fma2(s[6], kA[6], a0); a1 = fma2(s[7], kA[7], a1);
        a0 = add2(a0, a1);
        float x, y; upk2(a0, x, y);
        float sk = x + y;
        sk += __shfl_xor_sync(~0u, sk, 1);
        sk += __shfl_xor_sync(~0u, sk, 2);
        sk += __shfl_xor_sync(~0u, sk, 4);
        float delta = (vA - eA*sk) * bA;
        ull e2 = pk2(eA, eA), d2 = pk2(delta, delta);
        #pragma unroll
        for (int i=0;i<8;i++) s[i] = fma2(s[i], e2, mul2(kA[i], d2));
        // out = S^T q
        ull q0 = mul2(s[0], qA[0]), q1 = mul2(s[1], qA[1]);
        q0 = fma2(s[2], qA[2], q0); q1 = fma2(s[3], qA[3], q1);
        q0 = fma2(s[4], qA[4], q0); q1 = fma2(s[5], qA[5], q1);
        q0 = fma2(s[6], qA[6], q0); q1 = fma2(s[7], qA[7], q1);
        q0 = add2(q0, q1);
        float ox, oy; upk2(q0, ox, oy);
        float o = ox + oy;
        o += __shfl_xor_sync(~0u, o, 1);
        o += __shfl_xor_sync(~0u, o, 2);
        o += __shfl_xor_sync(~0u, o, 4);
        if (kg == 0) op[(size_t)t*VALDIM] = o;

        #pragma unroll
        for (int i=0;i<8;i++){ kA[i]=kB[i]; qA[i]=qB[i]; }
        vA=vB; eA=eB; bA=bB;
    }
}

// ------------ RMS norm + silu(z) gate ------------
__global__ __launch_bounds__(256) void gate_kernel(const float* __restrict__ nw) {
    int t = blockIdx.x;
    int warp = threadIdx.x>>5, lane = threadIdx.x&31;
    #pragma unroll
    for (int i=0;i<4;i++){
        int h = warp*4 + i;
        const float* cp = g_core + (size_t)t*VALDIM + h*128;
        float4 c = *(const float4*)(cp + lane*4);
        float ss = c.x*c.x + c.y*c.y + c.z*c.z + c.w*c.w;
        ss += __shfl_xor_sync(~0u, ss, 16);
        ss += __shfl_xor_sync(~0u, ss, 8);
        ss += __shfl_xor_sync(~0u, ss, 4);
        ss += __shfl_xor_sync(~0u, ss, 2);
        ss += __shfl_xor_sync(~0u, ss, 1);
        float sc = rsqrtf(ss*(1.f/128.f) + 1e-6f);
        const float* zp = g_qkvz + (size_t)t*NQKVZ + (h>>1)*768 + 512 + (h&1)*128;
        float4 z = *(const float4*)(zp + lane*4);
        float4 w = *(const float4*)(nw + lane*4);
        float4 o;
        o.x = c.x*sc*w.x * (z.x/(1.f+expf(-z.x)));
        o.y = c.y*sc*w.y * (z.y/(1.f+expf(-z.y)));
        o.z = c.z*sc*w.z * (z.z/(1.f+expf(-z.z)));
        o.w = c.w*sc*w.w * (z.w/(1.f+expf(-z.w)));
        *(float4*)(g_gated + (size_t)t*VALDIM + h*128 + lane*4) = o;
    }
}

extern "C" void kernel_launch(void* const* d_in, const int* in_sizes, int n_in,
                              void* d_out, int out_size) {
    const float* H     = (const float*)d_in[0];
    const float* Wqkvz = (const float*)d_in[1];
    const float* Wba   = (const float*)d_in[2];
    const float* convw = (const float*)d_in[3];
    const float* Alog  = (const float*)d_in[4];
    const float* dtb   = (const float*)d_in[5];
    const float* nw    = (const float*)d_in[6];
    const float* Wout  = (const float*)d_in[7];
    float* out = (float*)d_out;

    float *qkvz, *gated;
    __nv_bfloat16 *Hh,*Hl,*W1h,*W1l,*Gh,*Gl,*W2h,*W2l;
    cudaGetSymbolAddress((void**)&qkvz,  g_qkvz);
    cudaGetSymbolAddress((void**)&gated, g_gated);
    cudaGetSymbolAddress((void**)&Hh,  g_Hh);  cudaGetSymbolAddress((void**)&Hl,  g_Hl);
    cudaGetSymbolAddress((void**)&W1h, g_W1h); cudaGetSymbolAddress((void**)&W1l, g_W1l);
    cudaGetSymbolAddress((void**)&Gh,  g_Gh);  cudaGetSymbolAddress((void**)&Gl,  g_Gl);
    cudaGetSymbolAddress((void**)&W2h, g_W2h); cudaGetSymbolAddress((void**)&W2l, g_W2l);

    static int smem_set = 0;
    if (!smem_set) {
        cudaFuncSetAttribute(gemm_sp, cudaFuncAttributeMaxDynamicSharedMemorySize, 2*STG_BYTES);
        smem_set = 1;
    }

    split_ew<<<1024, 256>>>(H, Hh, Hl, (size_t)SEQ*HID/4);
    splitT  <<<dim3(NQKVZ/32, HID/32), 256>>>(Wqkvz, W1h, W1l, HID, NQKVZ);
    splitT  <<<dim3(HID/32, VALDIM/32), 256>>>(Wout, W2h, W2l, VALDIM, HID);

    gemm_sp<<<dim3(SEQ/128, NQKVZ/128), 256, 2*STG_BYTES>>>(Hh, Hl, W1h, W1l, qkvz, SEQ, NQKVZ, HID);
    gemm_ba<<<SEQ/4, 256>>>(H, Wba);
    conv_kernel<<<dim3(CONVD/128, SEQ/64), 128>>>(convw);
    prep_kernel<<<SEQ, 256>>>(Alog, dtb);
    scan_kernel<<<256, 128>>>();
    gate_kernel<<<SEQ, 256>>>(nw);

    split_ew<<<1024, 256>>>(gated, Gh, Gl, (size_t)SEQ*VALDIM/4);
    gemm_sp<<<dim3(SEQ/128, HID/128), 256, 2*STG_BYTES>>>(Gh, Gl, W2h, W2l, out, SEQ, HID, VALDIM);
}

// round 12
// speedup vs baseline: 2.7239x; 1.1896x over previous
#include <cuda_runtime.h>
#include <cuda_bf16.h>
#include <cuda_fp16.h>
#include <cstdint>

#define SEQ   4096
#define HID   2048
#define NQKVZ 12288
#define CONVD 8192
#define KEYDIM 2048
#define VALDIM 4096

typedef unsigned long long ull;

// ------------ scratch ------------
__device__ float g_qkvz [(size_t)SEQ * NQKVZ];
__device__ float g_ba   [SEQ * 64];
__device__ float g_mixed[(size_t)SEQ * CONVD];
__device__ float g_qn   [(size_t)SEQ * KEYDIM];
__device__ float g_kn   [(size_t)SEQ * KEYDIM];
__device__ float g_eg   [SEQ * 32];
__device__ float g_beta [SEQ * 32];
__device__ float g_core [(size_t)SEQ * VALDIM];
__device__ float g_gated[(size_t)SEQ * VALDIM];

// fp16 split activations (hi/lo) + fp16 weights (single, transposed [n][k])
__device__ __half g_Hh [(size_t)SEQ * HID];
__device__ __half g_Hl [(size_t)SEQ * HID];
__device__ __half g_W1 [(size_t)NQKVZ * HID];
__device__ __half g_Gh [(size_t)SEQ * VALDIM];
__device__ __half g_Gl [(size_t)SEQ * VALDIM];
__device__ __half g_W2 [(size_t)HID * VALDIM];

// ------------ f32x2 helpers ------------
__device__ __forceinline__ ull pk2(float a, float b){ ull r; asm("mov.b64 %0,{%1,%2};":"=l"(r):"f"(a),"f"(b)); return r; }
__device__ __forceinline__ void upk2(ull v, float& a, float& b){ asm("mov.b64 {%0,%1},%2;":"=f"(a),"=f"(b):"l"(v)); }
__device__ __forceinline__ ull fma2(ull a, ull b, ull c){ ull d; asm("fma.rn.f32x2 %0,%1,%2,%3;":"=l"(d):"l"(a),"l"(b),"l"(c)); return d; }
__device__ __forceinline__ ull mul2(ull a, ull b){ ull d; asm("mul.rn.f32x2 %0,%1,%2;":"=l"(d):"l"(a),"l"(b)); return d; }
__device__ __forceinline__ ull add2(ull a, ull b){ ull d; asm("add.rn.f32x2 %0,%1,%2;":"=l"(d):"l"(a),"l"(b)); return d; }

__device__ __forceinline__ void mma_f16(float* c, const unsigned* a, const unsigned* b){
    asm volatile("mma.sync.aligned.m16n8k16.row.col.f32.f16.f16.f32 "
        "{%0,%1,%2,%3},{%4,%5,%6,%7},{%8,%9},{%0,%1,%2,%3};\n"
        : "+f"(c[0]),"+f"(c[1]),"+f"(c[2]),"+f"(c[3])
        : "r"(a[0]),"r"(a[1]),"r"(a[2]),"r"(a[3]),"r"(b[0]),"r"(b[1]));
}
__device__ __forceinline__ void cp16(uint32_t dst, const void* src){
    asm volatile("cp.async.cg.shared.global [%0], [%1], 16;" :: "r"(dst), "l"(src));
}
__device__ __forceinline__ void ldsm4(unsigned* r, uint32_t a){
    asm volatile("ldmatrix.sync.aligned.m8n8.x4.shared.b16 {%0,%1,%2,%3},[%4];"
        : "=r"(r[0]),"=r"(r[1]),"=r"(r[2]),"=r"(r[3]) : "r"(a));
}
__device__ __forceinline__ void ldsm2(unsigned* r, uint32_t a){
    asm volatile("ldmatrix.sync.aligned.m8n8.x2.shared.b16 {%0,%1},[%2];"
        : "=r"(r[0]),"=r"(r[1]) : "r"(a));
}

// ------------ pipelined split-fp16 GEMM: C[M][N] = (Ah+Al)[M][K] * B^T, B [N][K] fp16
// stage: Ah 8KB | Al 8KB | B 8KB  (K-chunk = 32)
#define STG_BYTES 24576
__global__ __launch_bounds__(256, 2) void gemm_sp(const __half* __restrict__ Ah,
                                                  const __half* __restrict__ Al,
                                                  const __half* __restrict__ B,
                                                  float* __restrict__ C,
                                                  int M, int N, int K) {
    extern __shared__ char smem[];
    uint32_t sbase = (uint32_t)__cvta_generic_to_shared(smem);
    const int tid = threadIdx.x;
    const int bm = blockIdx.x*128, bn = blockIdx.y*128;
    const int warp = tid >> 5, lane = tid & 31;
    const int wm = (warp >> 2)*64, wn = (warp & 3)*32;

    float acc[4][4][4];
    #pragma unroll
    for (int i=0;i<4;i++)
      #pragma unroll
      for (int j=0;j<4;j++)
        #pragma unroll
        for (int k=0;k<4;k++) acc[i][j][k]=0.f;

    // 6 cp.async per thread per stage (2 per array)
    auto load_stage = [&](int st, int k0){
        uint32_t so = sbase + st*STG_BYTES;
        #pragma unroll
        for (int i=0;i<2;i++){
            int id  = tid + i*256;              // 0..511
            int row = id >> 2, c = id & 3;
            uint32_t d = row*64 + ((c ^ ((row>>1)&3))<<4);
            size_t ga = (size_t)(bm+row)*K + k0 + c*8;
            size_t gb = (size_t)(bn+row)*K + k0 + c*8;
            cp16(so          + d, Ah + ga);
            cp16(so +  8192  + d, Al + ga);
            cp16(so + 16384  + d, B  + gb);
        }
    };

    const int NK = K >> 5;
    load_stage(0, 0);
    asm volatile("cp.async.commit_group;");

    for (int it = 0; it < NK; it++) {
        if (it + 1 < NK) load_stage((it+1)&1, (it+1)*32);
        asm volatile("cp.async.commit_group;");
        asm volatile("cp.async.wait_group 1;");
        __syncthreads();

        uint32_t so = sbase + (it&1)*STG_BYTES;
        #pragma unroll
        for (int ks=0; ks<2; ks++){
            unsigned ah[4][4], al[4][4], bf[4][2];
            #pragma unroll
            for (int mt=0; mt<4; mt++){
                int row = wm + mt*16 + (lane&15);
                int ch  = ks*2 + (lane>>4);
                uint32_t off = row*64 + ((ch ^ ((row>>1)&3))<<4);
                ldsm4(ah[mt], so + off);
                ldsm4(al[mt], so + 8192 + off);
            }
            #pragma unroll
            for (int nt=0; nt<4; nt++){
                int row = wn + nt*8 + (lane&7);
                int ch  = ks*2 + ((lane&15)>>3);
                uint32_t off = row*64 + ((ch ^ ((row>>1)&3))<<4);
                ldsm2(bf[nt], so + 16384 + off);
            }
            #pragma unroll
            for (int mt=0; mt<4; mt++)
              #pragma unroll
              for (int nt=0; nt<4; nt++){
                  mma_f16(acc[mt][nt], ah[mt], bf[nt]);
                  mma_f16(acc[mt][nt], al[mt], bf[nt]);
              }
        }
        __syncthreads();
    }

    #pragma unroll
    for (int mt=0; mt<4; mt++){
        int r = bm + wm + mt*16 + (lane>>2);
        #pragma unroll
        for (int nt=0; nt<4; nt++){
            int c = bn + wn + nt*8 + (lane&3)*2;
            *(float2*)(C + (size_t) r   *N + c) = make_float2(acc[mt][nt][0], acc[mt][nt][1]);
            *(float2*)(C + (size_t)(r+8)*N + c) = make_float2(acc[mt][nt][2], acc[mt][nt][3]);
        }
    }
}

// ------------ elementwise fp32 -> fp16 hi/lo split ------------
__global__ __launch_bounds__(256) void split_ew(const float* __restrict__ in,
                                                __half* __restrict__ oh,
                                                __half* __restrict__ ol,
                                                size_t n4) {
    size_t i = (size_t)blockIdx.x*256 + threadIdx.x;
    size_t stride = (size_t)gridDim.x*256;
    for (; i < n4; i += stride) {
        float4 v = ((const float4*)in)[i];
        __half h0=__float2half_rn(v.x), h1=__float2half_rn(v.y),
               h2=__float2half_rn(v.z), h3=__float2half_rn(v.w);
        __half2 H0 = {h0,h1}, H1 = {h2,h3};
        __half2 L0 = {__float2half_rn(v.x-__half2float(h0)),
                      __float2half_rn(v.y-__half2float(h1))};
        __half2 L1 = {__float2half_rn(v.z-__half2float(h2)),
                      __float2half_rn(v.w-__half2float(h3))};
        ((__half2*)oh)[2*i]   = H0; ((__half2*)oh)[2*i+1] = H1;
        ((__half2*)ol)[2*i]   = L0; ((__half2*)ol)[2*i+1] = L1;
    }
}

// ------------ transpose + round: in[K][N] fp32 -> out[n][k] fp16 ------------
__global__ __launch_bounds__(256) void splitT(const float* __restrict__ in,
                                              __half* __restrict__ oh,
                                              int K, int N) {
    __shared__ float tile[32][33];
    int n0 = blockIdx.x*32, k0 = blockIdx.y*32;
    int tx = threadIdx.x & 31, ty = threadIdx.x >> 5;
    #pragma unroll
    for (int j = 0; j < 32; j += 8)
        tile[ty+j][tx] = in[(size_t)(k0+ty+j)*N + n0 + tx];
    __syncthreads();
    #pragma unroll
    for (int j = 0; j < 32; j += 8)
        oh[(size_t)(n0+ty+j)*K + k0 + tx] = __float2half_rn(tile[tx][ty+j]);
}

// ------------ ba = H @ W_ba ------------
__global__ __launch_bounds__(256) void gemm_ba(const float* __restrict__ A,
                                               const float* __restrict__ B) {
    int r = blockIdx.x*4 + (threadIdx.x>>6);
    int c = threadIdx.x & 63;
    const float* ar = A + (size_t)r*HID;
    float acc = 0.f;
    #pragma unroll 4
    for (int k=0;k<HID;k+=4){
        float4 a = *(const float4*)(ar+k);
        acc += a.x*B[(k  )*64+c] + a.y*B[(k+1)*64+c]
             + a.z*B[(k+2)*64+c] + a.w*B[(k+3)*64+c];
    }
    g_ba[r*64+c] = acc;
}

// ------------ causal depthwise conv(4) + silu ------------
__global__ __launch_bounds__(128) void conv_kernel(const float* __restrict__ cw) {
    int c  = blockIdx.x*128 + threadIdx.x;
    int t0 = blockIdx.y*64;
    int col;
    if (c < 2048)      col = (c>>7)*768 + (c&127);
    else if (c < 4096) { int cc=c-2048; col = (cc>>7)*768 + 128 + (cc&127); }
    else               { int cc=c-4096; col = (cc>>8)*768 + 256 + (cc&255); }
    float4 w = *(const float4*)(cw + c*4);
    float x0=0.f, x1=0.f, x2=0.f;
    if (t0 >= 3) {
        x0 = g_qkvz[(size_t)(t0-3)*NQKVZ + col];
        x1 = g_qkvz[(size_t)(t0-2)*NQKVZ + col];
        x2 = g_qkvz[(size_t)(t0-1)*NQKVZ + col];
    }
    #pragma unroll 4
    for (int t=t0; t<t0+64; t++) {
        float x3 = g_qkvz[(size_t)t*NQKVZ + col];
        float y = x0*w.x + x1*w.y + x2*w.z + x3*w.w;
        g_mixed[(size_t)t*CONVD + c] = y / (1.f + expf(-y));
        x0=x1; x1=x2; x2=x3;
    }
}

// ------------ l2norm q/k, gates ------------
__global__ __launch_bounds__(256) void prep_kernel(const float* __restrict__ Alog,
                                                   const float* __restrict__ dtb) {
    int t = blockIdx.x;
    int warp = threadIdx.x>>5, lane = threadIdx.x&31;
    #pragma unroll
    for (int i=0;i<4;i++){
        int row = warp*4+i;
        int isK = row>=16, h = row&15;
        const float* src = g_mixed + (size_t)t*CONVD + (isK?2048:0) + h*128;
        float4 v = *(const float4*)(src + lane*4);
        float ss = v.x*v.x+v.y*v.y+v.z*v.z+v.w*v.w;
        ss += __shfl_xor_sync(~0u, ss, 16);
        ss += __shfl_xor_sync(~0u, ss, 8);
        ss += __shfl_xor_sync(~0u, ss, 4);
        ss += __shfl_xor_sync(~0u, ss, 2);
        ss += __shfl_xor_sync(~0u, ss, 1);
        float sc = rsqrtf(ss + 1e-6f);
        if (!isK) sc *= 0.08838834764831845f;
        float* dst = (isK ? g_kn : g_qn) + (size_t)t*KEYDIM + h*128 + lane*4;
        *(float4*)dst = make_float4(v.x*sc, v.y*sc, v.z*sc, v.w*sc);
    }
    if (threadIdx.x < 32) {
        int h32 = threadIdx.x, h16 = h32>>1, j = h32&1;
        float b = g_ba[t*64 + h16*4 + j];
        float a = g_ba[t*64 + h16*4 + 2 + j];
        float x = a + dtb[h32];
        float sp = (x > 20.f) ? x : log1pf(expf(x));
        g_eg  [t*32 + h32] = expf(-expf(Alog[h32]) * sp);
        g_beta[t*32 + h32] = 1.f / (1.f + expf(-b));
    }
}

// ------------ gated delta-rule scan ------------
__global__ __launch_bounds__(128) void scan_kernel() {
    int h = blockIdx.x>>3, vb = blockIdx.x&7;
    int warp = threadIdx.x>>5, lane = threadIdx.x&31;
    int kg = lane&7, vg = lane>>3;
    int v = vb*16 + warp*4 + vg, h16 = h>>1;
    const float* kp = g_kn + h16*128 + kg*16;
    const float* qp = g_qn + h16*128 + kg*16;
    const float* vp = g_mixed + 4096 + h*128 + v;
    const float* ep = g_eg + h;
    const float* bp = g_beta + h;
    float* op = g_core + h*128 + v;

    ull s[8];
    #pragma unroll
    for (int i=0;i<8;i++) s[i]=0ull;

    ull kA[8], qA[8]; float vA, eA, bA;
    auto LOAD = [&](int t, ull* kf, ull* qf, float& vv, float& ee, float& bt){
        const ulonglong2* kk = (const ulonglong2*)(kp + (size_t)t*KEYDIM);
        const ulonglong2* qq = (const ulonglong2*)(qp + (size_t)t*KEYDIM);
        #pragma unroll
        for (int i=0;i<4;i++){
            ulonglong2 a = kk[i]; kf[2*i]=a.x; kf[2*i+1]=a.y;
            ulonglong2 b = qq[i]; qf[2*i]=b.x; qf[2*i+1]=b.y;
        }
        vv = vp[(size_t)t*CONVD];
        ee = ep[(size_t)t*32];
        bt = bp[(size_t)t*32];
    };
    LOAD(0, kA, qA, vA, eA, bA);

    #pragma unroll 2
    for (int t=0; t<SEQ; t++) {
        ull kB[8], qB[8]; float vB, eB, bB;
        if (t+1 < SEQ) LOAD(t+1, kB, qB, vB, eB, bB);

        ull a0 = mul2(s[0], kA[0]), a1 = mul2(s[1], kA[1]);
        a0 = fma2(s[2], kA[2], a0); a1 = fma2(s[3], kA[3], a1);
        a0 = fma2(s[4], kA[4], a0); a1 = fma2(s[5], kA[5], a1);
        a0 = fma2(s[6], kA[6], a0); a1 = fma2(s[7], kA[7], a1);
        a0 = add2(a0, a1);
        float x, y; upk2(a0, x, y);
        float sk = x + y;
        sk += __shfl_xor_sync(~0u, sk, 1);
        sk += __shfl_xor_sync(~0u, sk, 2);
        sk += __shfl_xor_sync(~0u, sk, 4);
        float delta = (vA - eA*sk) * bA;
        ull e2 = pk2(eA, eA), d2 = pk2(delta, delta);
        #pragma unroll
        for (int i=0;i<8;i++) s[i] = fma2(s[i], e2, mul2(kA[i], d2));
        ull q0 = mul2(s[0], qA[0]), q1 = mul2(s[1], qA[1]);
        q0 = fma2(s[2], qA[2], q0); q1 = fma2(s[3], qA[3], q1);
        q0 = fma2(s[4], qA[4], q0); q1 = fma2(s[5], qA[5], q1);
        q0 = fma2(s[6], qA[6], q0); q1 = fma2(s[7], qA[7], q1);
        q0 = add2(q0, q1);
        float ox, oy; upk2(q0, ox, oy);
        float o = ox + oy;
        o += __shfl_xor_sync(~0u, o, 1);
        o += __shfl_xor_sync(~0u, o, 2);
        o += __shfl_xor_sync(~0u, o, 4);
        if (kg == 0) op[(size_t)t*VALDIM] = o;

        #pragma unroll
        for (int i=0;i<8;i++){ kA[i]=kB[i]; qA[i]=qB[i]; }
        vA=vB; eA=eB; bA=bB;
    }
}

// ------------ RMS norm + silu(z) gate (fused fp16 split output) ------------
__global__ __launch_bounds__(256) void gate_kernel(const float* __restrict__ nw) {
    int t = blockIdx.x;
    int warp = threadIdx.x>>5, lane = threadIdx.x&31;
    #pragma unroll
    for (int i=0;i<4;i++){
        int h = warp*4 + i;
        const float* cp = g_core + (size_t)t*VALDIM + h*128;
        float4 c = *(const float4*)(cp + lane*4);
        float ss = c.x*c.x + c.y*c.y + c.z*c.z + c.w*c.w;
        ss += __shfl_xor_sync(~0u, ss, 16);
        ss += __shfl_xor_sync(~0u, ss, 8);
        ss += __shfl_xor_sync(~0u, ss, 4);
        ss += __shfl_xor_sync(~0u, ss, 2);
        ss += __shfl_xor_sync(~0u, ss, 1);
        float sc = rsqrtf(ss*(1.f/128.f) + 1e-6f);
        const float* zp = g_qkvz + (size_t)t*NQKVZ + (h>>1)*768 + 512 + (h&1)*128;
        float4 z = *(const float4*)(zp + lane*4);
        float4 w = *(const float4*)(nw + lane*4);
        float4 o;
        o.x = c.x*sc*w.x * (z.x/(1.f+expf(-z.x)));
        o.y = c.y*sc*w.y * (z.y/(1.f+expf(-z.y)));
        o.z = c.z*sc*w.z * (z.z/(1.f+expf(-z.z)));
        o.w = c.w*sc*w.w * (z.w/(1.f+expf(-z.w)));
        size_t base = (size_t)t*VALDIM + h*128 + lane*4;
        __half h0=__float2half_rn(o.x), h1=__float2half_rn(o.y),
               h2=__float2half_rn(o.z), h3=__float2half_rn(o.w);
        __half2 H0={h0,h1}, H1={h2,h3};
        __half2 L0={__float2half_rn(o.x-__half2float(h0)), __float2half_rn(o.y-__half2float(h1))};
        __half2 L1={__float2half_rn(o.z-__half2float(h2)), __float2half_rn(o.w-__half2float(h3))};
        *(__half2*)(g_Gh + base)     = H0; *(__half2*)(g_Gh + base + 2) = H1;
        *(__half2*)(g_Gl + base)     = L0; *(__half2*)(g_Gl + base + 2) = L1;
    }
}

extern "C" void kernel_launch(void* const* d_in, const int* in_sizes, int n_in,
                              void* d_out, int out_size) {
    const float* H     = (const float*)d_in[0];
    const float* Wqkvz = (const float*)d_in[1];
    const float* Wba   = (const float*)d_in[2];
    const float* convw = (const float*)d_in[3];
    const float* Alog  = (const float*)d_in[4];
    const float* dtb   = (const float*)d_in[5];
    const float* nw    = (const float*)d_in[6];
    const float* Wout  = (const float*)d_in[7];
    float* out = (float*)d_out;

    float *qkvz;
    __half *Hh,*Hl,*W1,*Gh,*Gl,*W2;
    cudaGetSymbolAddress((void**)&qkvz, g_qkvz);
    cudaGetSymbolAddress((void**)&Hh, g_Hh); cudaGetSymbolAddress((void**)&Hl, g_Hl);
    cudaGetSymbolAddress((void**)&W1, g_W1);
    cudaGetSymbolAddress((void**)&Gh, g_Gh); cudaGetSymbolAddress((void**)&Gl, g_Gl);
    cudaGetSymbolAddress((void**)&W2, g_W2);

    static int smem_set = 0;
    if (!smem_set) {
        cudaFuncSetAttribute(gemm_sp, cudaFuncAttributeMaxDynamicSharedMemorySize, 2*STG_BYTES);
        smem_set = 1;
    }

    split_ew<<<1024, 256>>>(H, Hh, Hl, (size_t)SEQ*HID/4);
    splitT  <<<dim3(NQKVZ/32, HID/32), 256>>>(Wqkvz, W1, HID, NQKVZ);
    splitT  <<<dim3(HID/32, VALDIM/32), 256>>>(Wout, W2, VALDIM, HID);

    gemm_sp<<<dim3(SEQ/128, NQKVZ/128), 256, 2*STG_BYTES>>>(Hh, Hl, W1, qkvz, SEQ, NQKVZ, HID);
    gemm_ba<<<SEQ/4, 256>>>(H, Wba);
    conv_kernel<<<dim3(CONVD/128, SEQ/64), 128>>>(convw);
    prep_kernel<<<SEQ, 256>>>(Alog, dtb);
    scan_kernel<<<256, 128>>>();
    gate_kernel<<<SEQ, 256>>>(nw);

    gemm_sp<<<dim3(SEQ/128, HID/128), 256, 2*STG_BYTES>>>(Gh, Gl, W2, out, SEQ, HID, VALDIM);
}

// round 13
// speedup vs baseline: 2.7828x; 1.0216x over previous
#include <cuda_runtime.h>
#include <cuda_bf16.h>
#include <cuda_fp16.h>
#include <cstdint>

#define SEQ   4096
#define HID   2048
#define NQKVZ 12288
#define CONVD 8192
#define KEYDIM 2048
#define VALDIM 4096

typedef unsigned long long ull;

// ------------ scratch ------------
__device__ float g_qkvz [(size_t)SEQ * NQKVZ];
__device__ float g_ba   [SEQ * 64];
__device__ float g_mixed[(size_t)SEQ * CONVD];
__device__ float g_qn   [(size_t)SEQ * KEYDIM];
__device__ float g_kn   [(size_t)SEQ * KEYDIM];
__device__ float g_eg   [SEQ * 32];
__device__ float g_beta [SEQ * 32];
__device__ float g_core [(size_t)SEQ * VALDIM];

__device__ __half g_Hh [(size_t)SEQ * HID];
__device__ __half g_Hl [(size_t)SEQ * HID];
__device__ __half g_W1 [(size_t)NQKVZ * HID];
__device__ __half g_Gh [(size_t)SEQ * VALDIM];
__device__ __half g_Gl [(size_t)SEQ * VALDIM];
__device__ __half g_W2 [(size_t)HID * VALDIM];

// ------------ f32x2 helpers ------------
__device__ __forceinline__ ull pk2(float a, float b){ ull r; asm("mov.b64 %0,{%1,%2};":"=l"(r):"f"(a),"f"(b)); return r; }
__device__ __forceinline__ void upk2(ull v, float& a, float& b){ asm("mov.b64 {%0,%1},%2;":"=f"(a),"=f"(b):"l"(v)); }
__device__ __forceinline__ ull fma2(ull a, ull b, ull c){ ull d; asm("fma.rn.f32x2 %0,%1,%2,%3;":"=l"(d):"l"(a),"l"(b),"l"(c)); return d; }
__device__ __forceinline__ ull mul2(ull a, ull b){ ull d; asm("mul.rn.f32x2 %0,%1,%2;":"=l"(d):"l"(a),"l"(b)); return d; }
__device__ __forceinline__ ull add2(ull a, ull b){ ull d; asm("add.rn.f32x2 %0,%1,%2;":"=l"(d):"l"(a),"l"(b)); return d; }

__device__ __forceinline__ void mma_f16(float* c, const unsigned* a, const unsigned* b){
    asm volatile("mma.sync.aligned.m16n8k16.row.col.f32.f16.f16.f32 "
        "{%0,%1,%2,%3},{%4,%5,%6,%7},{%8,%9},{%0,%1,%2,%3};\n"
        : "+f"(c[0]),"+f"(c[1]),"+f"(c[2]),"+f"(c[3])
        : "r"(a[0]),"r"(a[1]),"r"(a[2]),"r"(a[3]),"r"(b[0]),"r"(b[1]));
}
__device__ __forceinline__ void cp16(uint32_t dst, const void* src){
    asm volatile("cp.async.cg.shared.global [%0], [%1], 16;" :: "r"(dst), "l"(src));
}
__device__ __forceinline__ void ldsm4(unsigned* r, uint32_t a){
    asm volatile("ldmatrix.sync.aligned.m8n8.x4.shared.b16 {%0,%1,%2,%3},[%4];"
        : "=r"(r[0]),"=r"(r[1]),"=r"(r[2]),"=r"(r[3]) : "r"(a));
}
__device__ __forceinline__ void ldsm2(unsigned* r, uint32_t a){
    asm volatile("ldmatrix.sync.aligned.m8n8.x2.shared.b16 {%0,%1},[%2];"
        : "=r"(r[0]),"=r"(r[1]) : "r"(a));
}

// ------------ 3-stage pipelined split-fp16 GEMM: C = (Ah+Al) * B^T, B [N][K] fp16
// stage layout: Ah 8KB | Al 8KB | B 8KB  (K-chunk = 32)
#define STG_BYTES 24576
#define NSTG 3
__global__ __launch_bounds__(256, 2) void gemm_sp(const __half* __restrict__ Ah,
                                                  const __half* __restrict__ Al,
                                                  const __half* __restrict__ B,
                                                  float* __restrict__ C,
                                                  int M, int N, int K) {
    extern __shared__ char smem[];
    uint32_t sbase = (uint32_t)__cvta_generic_to_shared(smem);
    const int tid = threadIdx.x;
    const int bm = blockIdx.x*128, bn = blockIdx.y*128;
    const int warp = tid >> 5, lane = tid & 31;
    const int wm = (warp >> 2)*64, wn = (warp & 3)*32;

    float acc[4][4][4];
    #pragma unroll
    for (int i=0;i<4;i++)
      #pragma unroll
      for (int j=0;j<4;j++)
        #pragma unroll
        for (int k=0;k<4;k++) acc[i][j][k]=0.f;

    // 6 cp.async per thread per stage (2 per array)
    auto load_stage = [&](int c){
        uint32_t so = sbase + (c % NSTG)*STG_BYTES;
        int k0 = c*32;
        #pragma unroll
        for (int i=0;i<2;i++){
            int id  = tid + i*256;              // 0..511
            int row = id >> 2, cc = id & 3;
            uint32_t d = row*64 + ((cc ^ ((row>>1)&3))<<4);
            size_t ga = (size_t)(bm+row)*K + k0 + cc*8;
            size_t gb = (size_t)(bn+row)*K + k0 + cc*8;
            cp16(so          + d, Ah + ga);
            cp16(so +  8192  + d, Al + ga);
            cp16(so + 16384  + d, B  + gb);
        }
        asm volatile("cp.async.commit_group;");
    };

    const int NK = K >> 5;
    load_stage(0);
    load_stage(1);

    for (int it = 0; it < NK; it++) {
        __syncthreads();                       // all warps done reading stage (it-1)%3
        if (it + 2 < NK) {
            load_stage(it + 2);                // writes stage (it+2)%3 == (it-1)%3
            asm volatile("cp.async.wait_group 2;");
        } else if (it + 1 < NK) {
            asm volatile("cp.async.wait_group 1;");
        } else {
            asm volatile("cp.async.wait_group 0;");
        }
        __syncthreads();                       // stage it visible to all warps

        uint32_t so = sbase + (it % NSTG)*STG_BYTES;
        #pragma unroll
        for (int ks=0; ks<2; ks++){
            unsigned ah[4][4], al[4][4], bf[4][2];
            #pragma unroll
            for (int mt=0; mt<4; mt++){
                int row = wm + mt*16 + (lane&15);
                int ch  = ks*2 + (lane>>4);
                uint32_t off = row*64 + ((ch ^ ((row>>1)&3))<<4);
                ldsm4(ah[mt], so + off);
                ldsm4(al[mt], so + 8192 + off);
            }
            #pragma unroll
            for (int nt=0; nt<4; nt++){
                int row = wn + nt*8 + (lane&7);
                int ch  = ks*2 + ((lane&15)>>3);
                uint32_t off = row*64 + ((ch ^ ((row>>1)&3))<<4);
                ldsm2(bf[nt], so + 16384 + off);
            }
            #pragma unroll
            for (int mt=0; mt<4; mt++)
              #pragma unroll
              for (int nt=0; nt<4; nt++){
                  mma_f16(acc[mt][nt], ah[mt], bf[nt]);
                  mma_f16(acc[mt][nt], al[mt], bf[nt]);
              }
        }
    }

    #pragma unroll
    for (int mt=0; mt<4; mt++){
        int r = bm + wm + mt*16 + (lane>>2);
        #pragma unroll
        for (int nt=0; nt<4; nt++){
            int c = bn + wn + nt*8 + (lane&3)*2;
            *(float2*)(C + (size_t) r   *N + c) = make_float2(acc[mt][nt][0], acc[mt][nt][1]);
            *(float2*)(C + (size_t)(r+8)*N + c) = make_float2(acc[mt][nt][2], acc[mt][nt][3]);
        }
    }
}

// ------------ elementwise fp32 -> fp16 hi/lo split ------------
__global__ __launch_bounds__(256) void split_ew(const float* __restrict__ in,
                                                __half* __restrict__ oh,
                                                __half* __restrict__ ol,
                                                size_t n4) {
    size_t i = (size_t)blockIdx.x*256 + threadIdx.x;
    size_t stride = (size_t)gridDim.x*256;
    for (; i < n4; i += stride) {
        float4 v = ((const float4*)in)[i];
        __half h0=__float2half_rn(v.x), h1=__float2half_rn(v.y),
               h2=__float2half_rn(v.z), h3=__float2half_rn(v.w);
        __half2 H0 = {h0,h1}, H1 = {h2,h3};
        __half2 L0 = {__float2half_rn(v.x-__half2float(h0)),
                      __float2half_rn(v.y-__half2float(h1))};
        __half2 L1 = {__float2half_rn(v.z-__half2float(h2)),
                      __float2half_rn(v.w-__half2float(h3))};
        ((__half2*)oh)[2*i]   = H0; ((__half2*)oh)[2*i+1] = H1;
        ((__half2*)ol)[2*i]   = L0; ((__half2*)ol)[2*i+1] = L1;
    }
}

// ------------ transpose + round: in[K][N] fp32 -> out[n][k] fp16 ------------
__global__ __launch_bounds__(256) void splitT(const float* __restrict__ in,
                                              __half* __restrict__ oh,
                                              int K, int N) {
    __shared__ float tile[32][33];
    int n0 = blockIdx.x*32, k0 = blockIdx.y*32;
    int tx = threadIdx.x & 31, ty = threadIdx.x >> 5;
    #pragma unroll
    for (int j = 0; j < 32; j += 8)
        tile[ty+j][tx] = in[(size_t)(k0+ty+j)*N + n0 + tx];
    __syncthreads();
    #pragma unroll
    for (int j = 0; j < 32; j += 8)
        oh[(size_t)(n0+ty+j)*K + k0 + tx] = __float2half_rn(tile[tx][ty+j]);
}

// ------------ ba = H @ W_ba ------------
__global__ __launch_bounds__(256) void gemm_ba(const float* __restrict__ A,
                                               const float* __restrict__ B) {
    int r = blockIdx.x*4 + (threadIdx.x>>6);
    int c = threadIdx.x & 63;
    const float* ar = A + (size_t)r*HID;
    float acc = 0.f;
    #pragma unroll 4
    for (int k=0;k<HID;k+=4){
        float4 a = *(const float4*)(ar+k);
        acc += a.x*B[(k  )*64+c] + a.y*B[(k+1)*64+c]
             + a.z*B[(k+2)*64+c] + a.w*B[(k+3)*64+c];
    }
    g_ba[r*64+c] = acc;
}

// ------------ causal depthwise conv(4) + silu ------------
__global__ __launch_bounds__(128) void conv_kernel(const float* __restrict__ cw) {
    int c  = blockIdx.x*128 + threadIdx.x;
    int t0 = blockIdx.y*64;
    int col;
    if (c < 2048)      col = (c>>7)*768 + (c&127);
    else if (c < 4096) { int cc=c-2048; col = (cc>>7)*768 + 128 + (cc&127); }
    else               { int cc=c-4096; col = (cc>>8)*768 + 256 + (cc&255); }
    float4 w = *(const float4*)(cw + c*4);
    float x0=0.f, x1=0.f, x2=0.f;
    if (t0 >= 3) {
        x0 = g_qkvz[(size_t)(t0-3)*NQKVZ + col];
        x1 = g_qkvz[(size_t)(t0-2)*NQKVZ + col];
        x2 = g_qkvz[(size_t)(t0-1)*NQKVZ + col];
    }
    #pragma unroll 4
    for (int t=t0; t<t0+64; t++) {
        float x3 = g_qkvz[(size_t)t*NQKVZ + col];
        float y = x0*w.x + x1*w.y + x2*w.z + x3*w.w;
        g_mixed[(size_t)t*CONVD + c] = y / (1.f + expf(-y));
        x0=x1; x1=x2; x2=x3;
    }
}

// ------------ l2norm q/k, gates ------------
__global__ __launch_bounds__(256) void prep_kernel(const float* __restrict__ Alog,
                                                   const float* __restrict__ dtb) {
    int t = blockIdx.x;
    int warp = threadIdx.x>>5, lane = threadIdx.x&31;
    #pragma unroll
    for (int i=0;i<4;i++){
        int row = warp*4+i;
        int isK = row>=16, h = row&15;
        const float* src = g_mixed + (size_t)t*CONVD + (isK?2048:0) + h*128;
        float4 v = *(const float4*)(src + lane*4);
        float ss = v.x*v.x+v.y*v.y+v.z*v.z+v.w*v.w;
        ss += __shfl_xor_sync(~0u, ss, 16);
        ss += __shfl_xor_sync(~0u, ss, 8);
        ss += __shfl_xor_sync(~0u, ss, 4);
        ss += __shfl_xor_sync(~0u, ss, 2);
        ss += __shfl_xor_sync(~0u, ss, 1);
        float sc = rsqrtf(ss + 1e-6f);
        if (!isK) sc *= 0.08838834764831845f;
        float* dst = (isK ? g_kn : g_qn) + (size_t)t*KEYDIM + h*128 + lane*4;
        *(float4*)dst = make_float4(v.x*sc, v.y*sc, v.z*sc, v.w*sc);
    }
    if (threadIdx.x < 32) {
        int h32 = threadIdx.x, h16 = h32>>1, j = h32&1;
        float b = g_ba[t*64 + h16*4 + j];
        float a = g_ba[t*64 + h16*4 + 2 + j];
        float x = a + dtb[h32];
        float sp = (x > 20.f) ? x : log1pf(expf(x));
        g_eg  [t*32 + h32] = expf(-expf(Alog[h32]) * sp);
        g_beta[t*32 + h32] = 1.f / (1.f + expf(-b));
    }
}

// ------------ gated delta-rule scan ------------
__global__ __launch_bounds__(128) void scan_kernel() {
    int h = blockIdx.x>>3, vb = blockIdx.x&7;
    int warp = threadIdx.x>>5, lane = threadIdx.x&31;
    int kg = lane&7, vg = lane>>3;
    int v = vb*16 + warp*4 + vg, h16 = h>>1;
    const float* kp = g_kn + h16*128 + kg*16;
    const float* qp = g_qn + h16*128 + kg*16;
    const float* vp = g_mixed + 4096 + h*128 + v;
    const float* ep = g_eg + h;
    const float* bp = g_beta + h;
    float* op = g_core + h*128 + v;

    ull s[8];
    #pragma unroll
    for (int i=0;i<8;i++) s[i]=0ull;

    ull kA[8], qA[8]; float vA, eA, bA;
    auto LOAD = [&](int t, ull* kf, ull* qf, float& vv, float& ee, float& bt){
        const ulonglong2* kk = (const ulonglong2*)(kp + (size_t)t*KEYDIM);
        const ulonglong2* qq = (const ulonglong2*)(qp + (size_t)t*KEYDIM);
        #pragma unroll
        for (int i=0;i<4;i++){
            ulonglong2 a = kk[i]; kf[2*i]=a.x; kf[2*i+1]=a.y;
            ulonglong2 b = qq[i]; qf[2*i]=b.x; qf[2*i+1]=b.y;
        }
        vv = vp[(size_t)t*CONVD];
        ee = ep[(size_t)t*32];
        bt = bp[(size_t)t*32];
    };
    LOAD(0, kA, qA, vA, eA, bA);

    #pragma unroll 2
    for (int t=0; t<SEQ; t++) {
        ull kB[8], qB[8]; float vB, eB, bB;
        if (t+1 < SEQ) LOAD(t+1, kB, qB, vB, eB, bB);

        ull a0 = mul2(s[0], kA[0]), a1 = mul2(s[1], kA[1]);
        a0 = fma2(s[2], kA[2], a0); a1 = fma2(s[3], kA[3], a1);
        a0 = fma2(s[4], kA[4], a0); a1 = fma2(s[5], kA[5], a1);
        a0 = fma2(s[6], kA[6], a0); a1 = fma2(s[7], kA[7], a1);
        a0 = add2(a0, a1);
        float x, y; upk2(a0, x, y);
        float sk = x + y;
        sk += __shfl_xor_sync(~0u, sk, 1);
        sk += __shfl_xor_sync(~0u, sk, 2);
        sk += __shfl_xor_sync(~0u, sk, 4);
        float delta = (vA - eA*sk) * bA;
        ull e2 = pk2(eA, eA), d2 = pk2(delta, delta);
        #pragma unroll
        for (int i=0;i<8;i++) s[i] = fma2(s[i], e2, mul2(kA[i], d2));
        ull q0 = mul2(s[0], qA[0]), q1 = mul2(s[1], qA[1]);
        q0 = fma2(s[2], qA[2], q0); q1 = fma2(s[3], qA[3], q1);
        q0 = fma2(s[4], qA[4], q0); q1 = fma2(s[5], qA[5], q1);
        q0 = fma2(s[6], qA[6], q0); q1 = fma2(s[7], qA[7], q1);
        q0 = add2(q0, q1);
        float ox, oy; upk2(q0, ox, oy);
        float o = ox + oy;
        o += __shfl_xor_sync(~0u, o, 1);
        o += __shfl_xor_sync(~0u, o, 2);
        o += __shfl_xor_sync(~0u, o, 4);
        if (kg == 0) op[(size_t)t*VALDIM] = o;

        #pragma unroll
        for (int i=0;i<8;i++){ kA[i]=kB[i]; qA[i]=qB[i]; }
        vA=vB; eA=eB; bA=bB;
    }
}

// ------------ RMS norm + silu(z) gate (fused fp16 split output) ------------
__global__ __launch_bounds__(256) void gate_kernel(const float* __restrict__ nw) {
    int t = blockIdx.x;
    int warp = threadIdx.x>>5, lane = threadIdx.x&31;
    #pragma unroll
    for (int i=0;i<4;i++){
        int h = warp*4 + i;
        const float* cp = g_core + (size_t)t*VALDIM + h*128;
        float4 c = *(const float4*)(cp + lane*4);
        float ss = c.x*c.x + c.y*c.y + c.z*c.z + c.w*c.w;
        ss += __shfl_xor_sync(~0u, ss, 16);
        ss += __shfl_xor_sync(~0u, ss, 8);
        ss += __shfl_xor_sync(~0u, ss, 4);
        ss += __shfl_xor_sync(~0u, ss, 2);
        ss += __shfl_xor_sync(~0u, ss, 1);
        float sc = rsqrtf(ss*(1.f/128.f) + 1e-6f);
        const float* zp = g_qkvz + (size_t)t*NQKVZ + (h>>1)*768 + 512 + (h&1)*128;
        float4 z = *(const float4*)(zp + lane*4);
        float4 w = *(const float4*)(nw + lane*4);
        float4 o;
        o.x = c.x*sc*w.x * (z.x/(1.f+expf(-z.x)));
        o.y = c.y*sc*w.y * (z.y/(1.f+expf(-z.y)));
        o.z = c.z*sc*w.z * (z.z/(1.f+expf(-z.z)));
        o.w = c.w*sc*w.w * (z.w/(1.f+expf(-z.w)));
        size_t base = (size_t)t*VALDIM + h*128 + lane*4;
        __half h0=__float2half_rn(o.x), h1=__float2half_rn(o.y),
               h2=__float2half_rn(o.z), h3=__float2half_rn(o.w);
        __half2 H0={h0,h1}, H1={h2,h3};
        __half2 L0={__float2half_rn(o.x-__half2float(h0)), __float2half_rn(o.y-__half2float(h1))};
        __half2 L1={__float2half_rn(o.z-__half2float(h2)), __float2half_rn(o.w-__half2float(h3))};
        *(__half2*)(g_Gh + base)     = H0; *(__half2*)(g_Gh + base + 2) = H1;
        *(__half2*)(g_Gl + base)     = L0; *(__half2*)(g_Gl + base + 2) = L1;
    }
}

extern "C" void kernel_launch(void* const* d_in, const int* in_sizes, int n_in,
                              void* d_out, int out_size) {
    const float* H     = (const float*)d_in[0];
    const float* Wqkvz = (const float*)d_in[1];
    const float* Wba   = (const float*)d_in[2];
    const float* convw = (const float*)d_in[3];
    const float* Alog  = (const float*)d_in[4];
    const float* dtb   = (const float*)d_in[5];
    const float* nw    = (const float*)d_in[6];
    const float* Wout  = (const float*)d_in[7];
    float* out = (float*)d_out;

    float *qkvz;
    __half *Hh,*Hl,*W1,*Gh,*Gl,*W2;
    cudaGetSymbolAddress((void**)&qkvz, g_qkvz);
    cudaGetSymbolAddress((void**)&Hh, g_Hh); cudaGetSymbolAddress((void**)&Hl, g_Hl);
    cudaGetSymbolAddress((void**)&W1, g_W1);
    cudaGetSymbolAddress((void**)&Gh, g_Gh); cudaGetSymbolAddress((void**)&Gl, g_Gl);
    cudaGetSymbolAddress((void**)&W2, g_W2);

    static int smem_set = 0;
    if (!smem_set) {
        cudaFuncSetAttribute(gemm_sp, cudaFuncAttributeMaxDynamicSharedMemorySize, NSTG*STG_BYTES);
        smem_set = 1;
    }

    split_ew<<<1024, 256>>>(H, Hh, Hl, (size_t)SEQ*HID/4);
    splitT  <<<dim3(NQKVZ/32, HID/32), 256>>>(Wqkvz, W1, HID, NQKVZ);
    splitT  <<<dim3(HID/32, VALDIM/32), 256>>>(Wout, W2, VALDIM, HID);

    gemm_sp<<<dim3(SEQ/128, NQKVZ/128), 256, NSTG*STG_BYTES>>>(Hh, Hl, W1, qkvz, SEQ, NQKVZ, HID);
    gemm_ba<<<SEQ/4, 256>>>(H, Wba);
    conv_kernel<<<dim3(CONVD/128, SEQ/64), 128>>>(convw);
    prep_kernel<<<SEQ, 256>>>(Alog, dtb);
    scan_kernel<<<256, 128>>>();
    gate_kernel<<<SEQ, 256>>>(nw);

    gemm_sp<<<dim3(SEQ/128, HID/128), 256, NSTG*STG_BYTES>>>(Gh, Gl, W2, out, SEQ, HID, VALDIM);
}